// round 7
// baseline (speedup 1.0000x reference)
#include <cuda_runtime.h>
#include <cstdint>
#include <cstddef>

#define D        8
#define HIDDEN   64
#define WIDTH    128
#define NTOT     65536
#define TSTEPS   8
#define NSUB     4
#define NSEG     7
#define NSTAGE   84          // 7 segs * 4 substeps * 3 stage-times
#define ROWU2    9           // ulonglong2 (16B) per param row: 8 W-pairs + 8 U'-pairs + {B,B,WU',WU'}
#define NCTA     148
#define SPC      444         // samples per CTA (148*444 = 65712 >= 65536), multiple of 4

typedef unsigned long long u64;

// Per-stage parameter rows, duplicated for f32x2 consumption.
// Row k: [w0w0 ... w7w7 | u0u0 ... u7u7 | B B WU WU]   (U, WU pre-scaled by 1/WIDTH)
__device__ float4 gParams[NSTAGE * WIDTH * ROWU2];   // 1.548 MB static device scratch

// ---------------- f32x2 helpers ----------------
__device__ __forceinline__ u64 pack2(float x, float y) {
    u64 r; asm("mov.b64 %0, {%1, %2};" : "=l"(r) : "f"(x), "f"(y)); return r;
}
__device__ __forceinline__ void unpack2(u64 v, float& x, float& y) {
    asm("mov.b64 {%0, %1}, %2;" : "=f"(x), "=f"(y) : "l"(v));
}
__device__ __forceinline__ u64 fma2(u64 a, u64 b, u64 c) {
    u64 d; asm("fma.rn.f32x2 %0, %1, %2, %3;" : "=l"(d) : "l"(a), "l"(b), "l"(c)); return d;
}
__device__ __forceinline__ u64 add2(u64 a, u64 b) {
    u64 d; asm("add.rn.f32x2 %0, %1, %2;" : "=l"(d) : "l"(a), "l"(b)); return d;
}
__device__ __forceinline__ u64 mul2(u64 a, u64 b) {
    u64 d; asm("mul.rn.f32x2 %0, %1, %2;" : "=l"(d) : "l"(a), "l"(b)); return d;
}
__device__ __forceinline__ float tanh_fast(float x) {
    float y; asm("tanh.approx.f32 %0, %1;" : "=f"(y) : "f"(x)); return y;
}
__device__ __forceinline__ u64 tanh2(u64 v) {
    float x, y; unpack2(v, x, y);
    return pack2(tanh_fast(x), tanh_fast(y));
}

// ---------------- cp.async helpers ----------------
__device__ __forceinline__ void cp16(void* dst_smem, const void* src) {
    uint32_t d = (uint32_t)__cvta_generic_to_shared(dst_smem);
    asm volatile("cp.async.cg.shared.global [%0], [%1], 16;" :: "r"(d), "l"(src));
}
__device__ __forceinline__ void cp_commit() {
    asm volatile("cp.async.commit_group;");
}
__device__ __forceinline__ void cp_wait1() {
    asm volatile("cp.async.wait_group 1;");
}

// ---------------- Kernel A: hypernetwork, 4 blocks per stage, warp-per-row ----------------
__global__ void __launch_bounds__(256) hyper_kernel(
    const float* __restrict__ ts,
    const float* __restrict__ w1, const float* __restrict__ b1,
    const float* __restrict__ w2, const float* __restrict__ b2,
    const float* __restrict__ w3, const float* __restrict__ b3)
{
    const int s   = blockIdx.x >> 2;     // stage 0..83
    const int q   = blockIdx.x & 3;      // quarter 0..3 (k in [32q, 32q+32))
    const int seg = s / 12;
    const int sub = (s % 12) / 3;
    const int st  = s % 3;

    const float t0 = ts[seg];
    const float t1 = ts[seg + 1];
    const float dt = (t1 - t0) * (1.0f / NSUB);
    const float t  = t0 + sub * dt + (st == 0 ? 0.0f : (st == 1 ? 0.5f * dt : dt));

    __shared__ float h1s[HIDDEN];
    __shared__ float h2s[HIDDEN];
    __shared__ float ps[800];            // 3*256 rows (W,U,G quarter) + 32 B rows

    const int tid  = threadIdx.x;
    const int wrp  = tid >> 5;
    const int lane = tid & 31;

    if (tid < HIDDEN)
        h1s[tid] = tanhf(w1[tid] * t + b1[tid]);
    __syncthreads();

    if (tid < HIDDEN) {
        float acc = b2[tid];
        const float* wr = w2 + tid * HIDDEN;
        #pragma unroll 8
        for (int j = 0; j < HIDDEN; j++) acc += wr[j] * h1s[j];
        h2s[tid] = tanhf(acc);
    }
    __syncthreads();

    // 800 rows of the w3 GEMV needed by this quarter; warp-per-row, coalesced.
    for (int i = wrp; i < 800; i += 8) {
        int r;
        if (i < 768) {
            const int chunk  = i >> 8;           // 0=W, 1=U, 2=G
            const int within = i & 255;
            r = chunk * (WIDTH * D) + q * 256 + within;
        } else {
            r = 3 * WIDTH * D + q * 32 + (i - 768);
        }
        const float* wr = w3 + (size_t)r * HIDDEN;
        float acc = wr[lane] * h2s[lane] + wr[lane + 32] * h2s[lane + 32];
        #pragma unroll
        for (int off = 16; off > 0; off >>= 1)
            acc += __shfl_xor_sync(0xFFFFFFFFu, acc, off);
        if (lane == 0) ps[i] = acc + b3[r];
    }
    __syncthreads();

    // Combine: 32 k-rows of this quarter
    if (tid < 32) {
        const int kl = tid;
        const int k  = q * 32 + kl;
        float* out = (float*)gParams + ((size_t)s * WIDTH + k) * (ROWU2 * 4);
        const float B = ps[768 + kl];
        float wu = 0.0f;
        #pragma unroll
        for (int j = 0; j < D; j++) {
            const float W  = ps[kl * D + j];
            const float Ur = ps[256 + kl * D + j];
            const float G  = ps[512 + kl * D + j];
            const float U  = Ur * (1.0f / (1.0f + __expf(-G)));
            wu += W * U;
            const float Us = U * (1.0f / WIDTH);      // pre-scale
            out[2 * j]          = W;  out[2 * j + 1]      = W;
            out[16 + 2 * j]     = Us; out[16 + 2 * j + 1] = Us;
        }
        const float wus = wu * (1.0f / WIDTH);
        out[32] = B;   out[33] = B;
        out[34] = wus; out[35] = wus;
    }
}

// ---------------- Kernel B: RK4, 4 samples/thread (two f32x2 pair-groups) ----------------

__device__ __forceinline__ void prefetch_stage(ulonglong2* sp, const ulonglong2* __restrict__ src, int tid)
{
    #pragma unroll 1
    for (int i = tid; i < WIDTH * ROWU2; i += 128)
        cp16(sp + i, src + i);
    cp_commit();
}

// zs/dz: 16 u64 = two groups of 8 dims; dl[2] per-group trace accumulators.
__device__ __forceinline__ void rhs4(const u64* __restrict__ zs, u64* __restrict__ dz,
                                     u64 dl[2], const ulonglong2* __restrict__ sp)
{
    const u64 NEG1 = pack2(-1.0f, -1.0f);
    u64 tr0 = 0ULL, tr1 = 0ULL;
    #pragma unroll
    for (int j = 0; j < 16; j++) dz[j] = 0ULL;

    #pragma unroll 2
    for (int k = 0; k < WIDTH; k++) {
        const ulonglong2* rp = sp + k * ROWU2;
        const ulonglong2 q0 = rp[0];
        const ulonglong2 q1 = rp[1];
        const ulonglong2 q2 = rp[2];
        const ulonglong2 q3 = rp[3];
        const ulonglong2 qb = rp[8];   // (B,B) , (WU',WU')

        // group 0 dot
        u64 s0 = fma2(q0.x, zs[0], qb.x);
        u64 s1 = mul2(q0.y, zs[1]);
        s0 = fma2(q1.x, zs[2], s0);
        s1 = fma2(q1.y, zs[3], s1);
        s0 = fma2(q2.x, zs[4], s0);
        s1 = fma2(q2.y, zs[5], s1);
        s0 = fma2(q3.x, zs[6], s0);
        s1 = fma2(q3.y, zs[7], s1);
        // group 1 dot
        u64 t0 = fma2(q0.x, zs[8],  qb.x);
        u64 t1 = mul2(q0.y, zs[9]);
        t0 = fma2(q1.x, zs[10], t0);
        t1 = fma2(q1.y, zs[11], t1);
        t0 = fma2(q2.x, zs[12], t0);
        t1 = fma2(q2.y, zs[13], t1);
        t0 = fma2(q3.x, zs[14], t0);
        t1 = fma2(q3.y, zs[15], t1);

        const u64 h0 = tanh2(add2(s0, s1));
        const u64 h1 = tanh2(add2(t0, t1));

        const ulonglong2 u0 = rp[4];
        const ulonglong2 u1 = rp[5];
        const ulonglong2 u2 = rp[6];
        const ulonglong2 u3 = rp[7];
        dz[0]  = fma2(h0, u0.x, dz[0]);
        dz[1]  = fma2(h0, u0.y, dz[1]);
        dz[2]  = fma2(h0, u1.x, dz[2]);
        dz[3]  = fma2(h0, u1.y, dz[3]);
        dz[4]  = fma2(h0, u2.x, dz[4]);
        dz[5]  = fma2(h0, u2.y, dz[5]);
        dz[6]  = fma2(h0, u3.x, dz[6]);
        dz[7]  = fma2(h0, u3.y, dz[7]);
        dz[8]  = fma2(h1, u0.x, dz[8]);
        dz[9]  = fma2(h1, u0.y, dz[9]);
        dz[10] = fma2(h1, u1.x, dz[10]);
        dz[11] = fma2(h1, u1.y, dz[11]);
        dz[12] = fma2(h1, u2.x, dz[12]);
        dz[13] = fma2(h1, u2.y, dz[13]);
        dz[14] = fma2(h1, u3.x, dz[14]);
        dz[15] = fma2(h1, u3.y, dz[15]);

        tr0 = fma2(fma2(h0, h0, NEG1), qb.y, tr0);   // accumulates -(1-h^2)*WU/WIDTH
        tr1 = fma2(fma2(h1, h1, NEG1), qb.y, tr1);
    }
    dl[0] = tr0;    // already scaled: rhs_logp = -trace
    dl[1] = tr1;
}

__device__ __forceinline__ void store_group(float* __restrict__ out, int t, int n0,
                                            const u64* z, u64 lp)
{
    float a[D], b[D];
    #pragma unroll
    for (int j = 0; j < D; j++) unpack2(z[j], a[j], b[j]);
    float4* pz = (float4*)(out + (size_t)t * NTOT * D + (size_t)n0 * D);
    pz[0] = make_float4(a[0], a[1], a[2], a[3]);
    pz[1] = make_float4(a[4], a[5], a[6], a[7]);
    pz[2] = make_float4(b[0], b[1], b[2], b[3]);
    pz[3] = make_float4(b[4], b[5], b[6], b[7]);
    float la, lb; unpack2(lp, la, lb);
    float2* pl = (float2*)(out + (size_t)TSTEPS * NTOT * D + (size_t)t * NTOT + n0);
    *pl = make_float2(la, lb);
}

__global__ void __launch_bounds__(128, 1) cnf_kernel(
    const float* __restrict__ ts,
    const float* __restrict__ z0,
    const float* __restrict__ lp0,
    float* __restrict__ out)
{
    __shared__ ulonglong2 spbuf[2][WIDTH * ROWU2];    // 2 x 18432 B

    const int tid  = threadIdx.x;
    const int base = blockIdx.x * SPC + tid * 4;      // 4 consecutive samples
    const bool valid = (tid * 4 < SPC) && (base + 4 <= NTOT);

    const ulonglong2* gp = (const ulonglong2*)gParams;

    ulonglong2* bufA = spbuf[0];
    ulonglong2* bufB = spbuf[1];
    prefetch_stage(bufA, gp, tid);

    u64 z[16], lp[2];
    #pragma unroll
    for (int j = 0; j < 16; j++) z[j] = 0ULL;
    lp[0] = lp[1] = 0ULL;

    if (valid) {
        #pragma unroll
        for (int g = 0; g < 2; g++) {
            const int n0 = base + 2 * g;
            const float4* pa = (const float4*)(z0 + (size_t)n0 * D);
            const float4 a0 = pa[0], a1 = pa[1], b0 = pa[2], b1 = pa[3];
            z[8*g + 0] = pack2(a0.x, b0.x); z[8*g + 1] = pack2(a0.y, b0.y);
            z[8*g + 2] = pack2(a0.z, b0.z); z[8*g + 3] = pack2(a0.w, b0.w);
            z[8*g + 4] = pack2(a1.x, b1.x); z[8*g + 5] = pack2(a1.y, b1.y);
            z[8*g + 6] = pack2(a1.z, b1.z); z[8*g + 7] = pack2(a1.w, b1.w);
            const float2 l = *(const float2*)(lp0 + n0);
            lp[g] = pack2(l.x, l.y);
            store_group(out, 0, n0, &z[8*g], lp[g]);
        }
    }

    for (int seg = 0; seg < NSEG; seg++) {
        const float dt  = (ts[seg + 1] - ts[seg]) * (1.0f / NSUB);
        const u64 dth = pack2(0.5f * dt, 0.5f * dt);
        const u64 dtf = pack2(dt, dt);
        const u64 dt6 = pack2(dt * (1.0f / 6.0f), dt * (1.0f / 6.0f));
        const u64 two = pack2(2.0f, 2.0f);

        for (int sub = 0; sub < NSUB; sub++) {
            const int sb = (seg * NSUB + sub) * 3;
            u64 acc[16], lacc[2], zs[16], dz[16], dl[2];

            // invariant: bufA has stage sb in flight (or landed)
            prefetch_stage(bufB, gp + (size_t)(sb + 1) * WIDTH * ROWU2, tid);
            cp_wait1();            // bufA landed
            __syncthreads();

            // k1
            if (valid) {
                rhs4(z, dz, dl, bufA);
                #pragma unroll
                for (int j = 0; j < 16; j++) { acc[j] = dz[j]; zs[j] = fma2(dth, dz[j], z[j]); }
                lacc[0] = dl[0]; lacc[1] = dl[1];
            }
            __syncthreads();
            prefetch_stage(bufA, gp + (size_t)(sb + 2) * WIDTH * ROWU2, tid);
            cp_wait1();            // bufB landed
            __syncthreads();

            // k2, k3 (same params)
            if (valid) {
                rhs4(zs, dz, dl, bufB);
                #pragma unroll
                for (int j = 0; j < 16; j++) { acc[j] = fma2(two, dz[j], acc[j]); zs[j] = fma2(dth, dz[j], z[j]); }
                lacc[0] = fma2(two, dl[0], lacc[0]); lacc[1] = fma2(two, dl[1], lacc[1]);

                rhs4(zs, dz, dl, bufB);
                #pragma unroll
                for (int j = 0; j < 16; j++) { acc[j] = fma2(two, dz[j], acc[j]); zs[j] = fma2(dtf, dz[j], z[j]); }
                lacc[0] = fma2(two, dl[0], lacc[0]); lacc[1] = fma2(two, dl[1], lacc[1]);
            }
            __syncthreads();
            {
                int nxt = sb + 3; if (nxt >= NSTAGE) nxt = 0;
                prefetch_stage(bufB, gp + (size_t)nxt * WIDTH * ROWU2, tid);
            }
            cp_wait1();            // bufA landed
            __syncthreads();

            // k4
            if (valid) {
                rhs4(zs, dz, dl, bufA);
                #pragma unroll
                for (int j = 0; j < 16; j++) { acc[j] = add2(acc[j], dz[j]); z[j] = fma2(dt6, acc[j], z[j]); }
                lacc[0] = add2(lacc[0], dl[0]); lacc[1] = add2(lacc[1], dl[1]);
                lp[0] = fma2(dt6, lacc[0], lp[0]);
                lp[1] = fma2(dt6, lacc[1], lp[1]);
            }
            __syncthreads();

            ulonglong2* tmp = bufA; bufA = bufB; bufB = tmp;
        }
        if (valid) {
            store_group(out, seg + 1, base,     &z[0], lp[0]);
            store_group(out, seg + 1, base + 2, &z[8], lp[1]);
        }
    }
}

// ---------------- launch ----------------
extern "C" void kernel_launch(void* const* d_in, const int* in_sizes, int n_in,
                              void* d_out, int out_size)
{
    const float* ts  = (const float*)d_in[0];
    const float* z0  = (const float*)d_in[1];
    const float* lp0 = (const float*)d_in[2];
    const float* w1  = (const float*)d_in[3];
    const float* b1  = (const float*)d_in[4];
    const float* w2  = (const float*)d_in[5];
    const float* b2  = (const float*)d_in[6];
    const float* w3  = (const float*)d_in[7];
    const float* b3  = (const float*)d_in[8];

    hyper_kernel<<<NSTAGE * 4, 256>>>(ts, w1, b1, w2, b2, w3, b3);
    cnf_kernel<<<NCTA, 128>>>(ts, z0, lp0, (float*)d_out);
}

// round 8
// speedup vs baseline: 1.1170x; 1.1170x over previous
#include <cuda_runtime.h>
#include <cstdint>
#include <cstddef>

#define D        8
#define HIDDEN   64
#define WIDTH    128
#define NTOT     65536
#define TSTEPS   8
#define NSUB     4
#define NSEG     7
#define NSTAGE   84          // 7 segs * 4 substeps * 3 stage-times
#define ROWU2    9           // ulonglong2 (16B) per param row
#define NCTA     148
#define SPC      444         // samples per CTA (148*444 = 65712 >= 65536), multiple of 4
#define THREADS  256
#define HALFROWS 64

typedef unsigned long long u64;

// Per-stage parameter rows, duplicated for f32x2 consumption.
// Row k: [w0w0 ... w7w7 | u0u0 ... u7u7 | B B WU WU]   (U, WU pre-scaled by 1/WIDTH)
__device__ float4 gParams[NSTAGE * WIDTH * ROWU2];   // 1.548 MB static device scratch

// dynamic smem: [0, 1152) bufA | [1152, 2304) bufB | xch: 18*256 u64 (36864 B)
#define SMEM_TOTAL (2 * WIDTH * ROWU2 * 16 + 18 * THREADS * 8)

// ---------------- f32x2 helpers ----------------
__device__ __forceinline__ u64 pack2(float x, float y) {
    u64 r; asm("mov.b64 %0, {%1, %2};" : "=l"(r) : "f"(x), "f"(y)); return r;
}
__device__ __forceinline__ void unpack2(u64 v, float& x, float& y) {
    asm("mov.b64 {%0, %1}, %2;" : "=f"(x), "=f"(y) : "l"(v));
}
__device__ __forceinline__ u64 fma2(u64 a, u64 b, u64 c) {
    u64 d; asm("fma.rn.f32x2 %0, %1, %2, %3;" : "=l"(d) : "l"(a), "l"(b), "l"(c)); return d;
}
__device__ __forceinline__ u64 add2(u64 a, u64 b) {
    u64 d; asm("add.rn.f32x2 %0, %1, %2;" : "=l"(d) : "l"(a), "l"(b)); return d;
}
__device__ __forceinline__ u64 mul2(u64 a, u64 b) {
    u64 d; asm("mul.rn.f32x2 %0, %1, %2;" : "=l"(d) : "l"(a), "l"(b)); return d;
}
__device__ __forceinline__ float tanh_fast(float x) {
    float y; asm("tanh.approx.f32 %0, %1;" : "=f"(y) : "f"(x)); return y;
}
__device__ __forceinline__ u64 tanh2(u64 v) {
    float x, y; unpack2(v, x, y);
    return pack2(tanh_fast(x), tanh_fast(y));
}

// ---------------- cp.async helpers ----------------
__device__ __forceinline__ void cp16(void* dst_smem, const void* src) {
    uint32_t d = (uint32_t)__cvta_generic_to_shared(dst_smem);
    asm volatile("cp.async.cg.shared.global [%0], [%1], 16;" :: "r"(d), "l"(src));
}
__device__ __forceinline__ void cp_commit() {
    asm volatile("cp.async.commit_group;");
}
__device__ __forceinline__ void cp_wait1() {
    asm volatile("cp.async.wait_group 1;");
}

// ---------------- Kernel A: hypernetwork, 4 blocks per stage, warp-per-row ----------------
__global__ void __launch_bounds__(256) hyper_kernel(
    const float* __restrict__ ts,
    const float* __restrict__ w1, const float* __restrict__ b1,
    const float* __restrict__ w2, const float* __restrict__ b2,
    const float* __restrict__ w3, const float* __restrict__ b3)
{
    const int s   = blockIdx.x >> 2;     // stage 0..83
    const int q   = blockIdx.x & 3;      // quarter 0..3
    const int seg = s / 12;
    const int sub = (s % 12) / 3;
    const int st  = s % 3;

    const float t0 = ts[seg];
    const float t1 = ts[seg + 1];
    const float dt = (t1 - t0) * (1.0f / NSUB);
    const float t  = t0 + sub * dt + (st == 0 ? 0.0f : (st == 1 ? 0.5f * dt : dt));

    __shared__ float h1s[HIDDEN];
    __shared__ float h2s[HIDDEN];
    __shared__ float ps[800];

    const int tid  = threadIdx.x;
    const int wrp  = tid >> 5;
    const int lane = tid & 31;

    if (tid < HIDDEN)
        h1s[tid] = tanhf(w1[tid] * t + b1[tid]);
    __syncthreads();

    if (tid < HIDDEN) {
        float acc = b2[tid];
        const float* wr = w2 + tid * HIDDEN;
        #pragma unroll 8
        for (int j = 0; j < HIDDEN; j++) acc += wr[j] * h1s[j];
        h2s[tid] = tanhf(acc);
    }
    __syncthreads();

    for (int i = wrp; i < 800; i += 8) {
        int r;
        if (i < 768) {
            const int chunk  = i >> 8;           // 0=W, 1=U, 2=G
            const int within = i & 255;
            r = chunk * (WIDTH * D) + q * 256 + within;
        } else {
            r = 3 * WIDTH * D + q * 32 + (i - 768);
        }
        const float* wr = w3 + (size_t)r * HIDDEN;
        float acc = wr[lane] * h2s[lane] + wr[lane + 32] * h2s[lane + 32];
        #pragma unroll
        for (int off = 16; off > 0; off >>= 1)
            acc += __shfl_xor_sync(0xFFFFFFFFu, acc, off);
        if (lane == 0) ps[i] = acc + b3[r];
    }
    __syncthreads();

    if (tid < 32) {
        const int kl = tid;
        const int k  = q * 32 + kl;
        float* out = (float*)gParams + ((size_t)s * WIDTH + k) * (ROWU2 * 4);
        const float B = ps[768 + kl];
        float wu = 0.0f;
        #pragma unroll
        for (int j = 0; j < D; j++) {
            const float W  = ps[kl * D + j];
            const float Ur = ps[256 + kl * D + j];
            const float G  = ps[512 + kl * D + j];
            const float U  = Ur * (1.0f / (1.0f + __expf(-G)));
            wu += W * U;
            const float Us = U * (1.0f / WIDTH);
            out[2 * j]          = W;  out[2 * j + 1]      = W;
            out[16 + 2 * j]     = Us; out[16 + 2 * j + 1] = Us;
        }
        const float wus = wu * (1.0f / WIDTH);
        out[32] = B;   out[33] = B;
        out[34] = wus; out[35] = wus;
    }
}

// ---------------- Kernel B: RK4, pair-of-threads per 4 samples, row-split ----------------

__device__ __forceinline__ void prefetch_stage(ulonglong2* sp, const ulonglong2* __restrict__ src, int tid)
{
    #pragma unroll 1
    for (int i = tid; i < WIDTH * ROWU2; i += THREADS)
        cp16(sp + i, src + i);
    cp_commit();
}

// Half-row RHS: rows [rowbase, rowbase+64). zs/dz: 16 u64 (two sample-pair groups).
__device__ __forceinline__ void rhs_half(const u64* __restrict__ zs, u64* __restrict__ dz,
                                         u64 dl[2], const ulonglong2* __restrict__ sp,
                                         int rowbase)
{
    const u64 NEG1 = pack2(-1.0f, -1.0f);
    u64 tr0 = 0ULL, tr1 = 0ULL;
    #pragma unroll
    for (int j = 0; j < 16; j++) dz[j] = 0ULL;

    const ulonglong2* rp = sp + rowbase * ROWU2;
    #pragma unroll 2
    for (int k = 0; k < HALFROWS; k++, rp += ROWU2) {
        const ulonglong2 q0 = rp[0];
        const ulonglong2 q1 = rp[1];
        const ulonglong2 q2 = rp[2];
        const ulonglong2 q3 = rp[3];
        const ulonglong2 qb = rp[8];   // (B,B) , (WU',WU')

        u64 s0 = fma2(q0.x, zs[0], qb.x);
        u64 s1 = mul2(q0.y, zs[1]);
        s0 = fma2(q1.x, zs[2], s0);
        s1 = fma2(q1.y, zs[3], s1);
        s0 = fma2(q2.x, zs[4], s0);
        s1 = fma2(q2.y, zs[5], s1);
        s0 = fma2(q3.x, zs[6], s0);
        s1 = fma2(q3.y, zs[7], s1);

        u64 t0 = fma2(q0.x, zs[8],  qb.x);
        u64 t1 = mul2(q0.y, zs[9]);
        t0 = fma2(q1.x, zs[10], t0);
        t1 = fma2(q1.y, zs[11], t1);
        t0 = fma2(q2.x, zs[12], t0);
        t1 = fma2(q2.y, zs[13], t1);
        t0 = fma2(q3.x, zs[14], t0);
        t1 = fma2(q3.y, zs[15], t1);

        const u64 h0 = tanh2(add2(s0, s1));
        const u64 h1 = tanh2(add2(t0, t1));

        const ulonglong2 u0 = rp[4];
        const ulonglong2 u1 = rp[5];
        const ulonglong2 u2 = rp[6];
        const ulonglong2 u3 = rp[7];
        dz[0]  = fma2(h0, u0.x, dz[0]);
        dz[1]  = fma2(h0, u0.y, dz[1]);
        dz[2]  = fma2(h0, u1.x, dz[2]);
        dz[3]  = fma2(h0, u1.y, dz[3]);
        dz[4]  = fma2(h0, u2.x, dz[4]);
        dz[5]  = fma2(h0, u2.y, dz[5]);
        dz[6]  = fma2(h0, u3.x, dz[6]);
        dz[7]  = fma2(h0, u3.y, dz[7]);
        dz[8]  = fma2(h1, u0.x, dz[8]);
        dz[9]  = fma2(h1, u0.y, dz[9]);
        dz[10] = fma2(h1, u1.x, dz[10]);
        dz[11] = fma2(h1, u1.y, dz[11]);
        dz[12] = fma2(h1, u2.x, dz[12]);
        dz[13] = fma2(h1, u2.y, dz[13]);
        dz[14] = fma2(h1, u3.x, dz[14]);
        dz[15] = fma2(h1, u3.y, dz[15]);

        tr0 = fma2(fma2(h0, h0, NEG1), qb.y, tr0);
        tr1 = fma2(fma2(h1, h1, NEG1), qb.y, tr1);
    }
    dl[0] = tr0;
    dl[1] = tr1;
}

// SoA exchange: xch[j*256 + tid], conflict-free STS.64/LDS.64
__device__ __forceinline__ void xwrite(u64* xch, int tid, const u64* dz, const u64 dl[2])
{
    #pragma unroll
    for (int j = 0; j < 16; j++) xch[j * THREADS + tid] = dz[j];
    xch[16 * THREADS + tid] = dl[0];
    xch[17 * THREADS + tid] = dl[1];
}
__device__ __forceinline__ void xcombine(const u64* xch, int p, u64* dz, u64 dl[2])
{
    #pragma unroll
    for (int j = 0; j < 16; j++) dz[j] = add2(dz[j], xch[j * THREADS + p]);
    dl[0] = add2(dl[0], xch[16 * THREADS + p]);
    dl[1] = add2(dl[1], xch[17 * THREADS + p]);
}

__device__ __forceinline__ void store_group(float* __restrict__ out, int t, int n0,
                                            const u64* z, u64 lp)
{
    float a[D], b[D];
    #pragma unroll
    for (int j = 0; j < D; j++) unpack2(z[j], a[j], b[j]);
    float4* pz = (float4*)(out + (size_t)t * NTOT * D + (size_t)n0 * D);
    pz[0] = make_float4(a[0], a[1], a[2], a[3]);
    pz[1] = make_float4(a[4], a[5], a[6], a[7]);
    pz[2] = make_float4(b[0], b[1], b[2], b[3]);
    pz[3] = make_float4(b[4], b[5], b[6], b[7]);
    float la, lb; unpack2(lp, la, lb);
    float2* pl = (float2*)(out + (size_t)TSTEPS * NTOT * D + (size_t)t * NTOT + n0);
    *pl = make_float2(la, lb);
}

__global__ void __launch_bounds__(THREADS, 1) cnf_kernel(
    const float* __restrict__ ts,
    const float* __restrict__ z0,
    const float* __restrict__ lp0,
    float* __restrict__ out)
{
    extern __shared__ ulonglong2 dynsm[];
    ulonglong2* bufA = dynsm;
    ulonglong2* bufB = dynsm + WIDTH * ROWU2;
    u64* xch = (u64*)(dynsm + 2 * WIDTH * ROWU2);

    const int tid     = threadIdx.x;
    const int half    = tid >> 7;          // 0: rows 0-63, 1: rows 64-127
    const int slot    = tid & 127;         // quad-sample slot
    const int rowbase = half * HALFROWS;
    const int base    = blockIdx.x * SPC + slot * 4;
    const bool valid  = (slot * 4 < SPC) && (base + 4 <= NTOT);

    const ulonglong2* gp = (const ulonglong2*)gParams;
    prefetch_stage(bufA, gp, tid);

    u64 z[16], lp[2];
    #pragma unroll
    for (int j = 0; j < 16; j++) z[j] = 0ULL;
    lp[0] = lp[1] = 0ULL;

    if (valid) {
        #pragma unroll
        for (int g = 0; g < 2; g++) {
            const int n0 = base + 2 * g;
            const float4* pa = (const float4*)(z0 + (size_t)n0 * D);
            const float4 a0 = pa[0], a1 = pa[1], b0 = pa[2], b1 = pa[3];
            z[8*g + 0] = pack2(a0.x, b0.x); z[8*g + 1] = pack2(a0.y, b0.y);
            z[8*g + 2] = pack2(a0.z, b0.z); z[8*g + 3] = pack2(a0.w, b0.w);
            z[8*g + 4] = pack2(a1.x, b1.x); z[8*g + 5] = pack2(a1.y, b1.y);
            z[8*g + 6] = pack2(a1.z, b1.z); z[8*g + 7] = pack2(a1.w, b1.w);
            const float2 l = *(const float2*)(lp0 + n0);
            lp[g] = pack2(l.x, l.y);
            if (half == 0) store_group(out, 0, n0, &z[8*g], lp[g]);
        }
    }

    const int prt = tid ^ 128;

    for (int seg = 0; seg < NSEG; seg++) {
        const float dt  = (ts[seg + 1] - ts[seg]) * (1.0f / NSUB);
        const u64 dth = pack2(0.5f * dt, 0.5f * dt);
        const u64 dtf = pack2(dt, dt);
        const u64 dt6 = pack2(dt * (1.0f / 6.0f), dt * (1.0f / 6.0f));
        const u64 two = pack2(2.0f, 2.0f);

        for (int sub = 0; sub < NSUB; sub++) {
            const int sb = (seg * NSUB + sub) * 3;
            u64 acc[16], lacc[2], zs[16], dz[16], dl[2];

            // invariant: bufA has stage sb in flight (or landed)
            prefetch_stage(bufB, gp + (size_t)(sb + 1) * WIDTH * ROWU2, tid);
            cp_wait1();            // bufA landed
            __syncthreads();

            // k1 (bufA = sb)
            if (valid) { rhs_half(z, dz, dl, bufA, rowbase); xwrite(xch, tid, dz, dl); }
            __syncthreads();       // partials visible; bufA reads done
            prefetch_stage(bufA, gp + (size_t)(sb + 2) * WIDTH * ROWU2, tid);
            if (valid) {
                xcombine(xch, prt, dz, dl);
                #pragma unroll
                for (int j = 0; j < 16; j++) { acc[j] = dz[j]; zs[j] = fma2(dth, dz[j], z[j]); }
                lacc[0] = dl[0]; lacc[1] = dl[1];
            }
            cp_wait1();            // bufB landed
            __syncthreads();       // xch consumed; bufB ready

            // k2 (bufB = sb+1)
            if (valid) { rhs_half(zs, dz, dl, bufB, rowbase); xwrite(xch, tid, dz, dl); }
            __syncthreads();
            if (valid) {
                xcombine(xch, prt, dz, dl);
                #pragma unroll
                for (int j = 0; j < 16; j++) { acc[j] = fma2(two, dz[j], acc[j]); zs[j] = fma2(dth, dz[j], z[j]); }
                lacc[0] = fma2(two, dl[0], lacc[0]); lacc[1] = fma2(two, dl[1], lacc[1]);
            }
            __syncthreads();       // xch consumed

            // k3 (bufB = sb+1, same params)
            if (valid) { rhs_half(zs, dz, dl, bufB, rowbase); xwrite(xch, tid, dz, dl); }
            __syncthreads();       // partials visible; bufB reads done
            {
                int nxt = sb + 3; if (nxt >= NSTAGE) nxt = 0;
                prefetch_stage(bufB, gp + (size_t)nxt * WIDTH * ROWU2, tid);
            }
            if (valid) {
                xcombine(xch, prt, dz, dl);
                #pragma unroll
                for (int j = 0; j < 16; j++) { acc[j] = fma2(two, dz[j], acc[j]); zs[j] = fma2(dtf, dz[j], z[j]); }
                lacc[0] = fma2(two, dl[0], lacc[0]); lacc[1] = fma2(two, dl[1], lacc[1]);
            }
            cp_wait1();            // bufA (sb+2) landed
            __syncthreads();       // xch consumed; bufA ready

            // k4 (bufA = sb+2)
            if (valid) { rhs_half(zs, dz, dl, bufA, rowbase); xwrite(xch, tid, dz, dl); }
            __syncthreads();
            if (valid) {
                xcombine(xch, prt, dz, dl);
                #pragma unroll
                for (int j = 0; j < 16; j++) { acc[j] = add2(acc[j], dz[j]); z[j] = fma2(dt6, acc[j], z[j]); }
                lacc[0] = add2(lacc[0], dl[0]); lacc[1] = add2(lacc[1], dl[1]);
                lp[0] = fma2(dt6, lacc[0], lp[0]);
                lp[1] = fma2(dt6, lacc[1], lp[1]);
            }
            __syncthreads();       // xch consumed before next substep rewrites

            ulonglong2* tmp = bufA; bufA = bufB; bufB = tmp;
        }
        if (valid && half == 0) {
            store_group(out, seg + 1, base,     &z[0], lp[0]);
            store_group(out, seg + 1, base + 2, &z[8], lp[1]);
        }
    }
}

// ---------------- launch ----------------
extern "C" void kernel_launch(void* const* d_in, const int* in_sizes, int n_in,
                              void* d_out, int out_size)
{
    const float* ts  = (const float*)d_in[0];
    const float* z0  = (const float*)d_in[1];
    const float* lp0 = (const float*)d_in[2];
    const float* w1  = (const float*)d_in[3];
    const float* b1  = (const float*)d_in[4];
    const float* w2  = (const float*)d_in[5];
    const float* b2  = (const float*)d_in[6];
    const float* w3  = (const float*)d_in[7];
    const float* b3  = (const float*)d_in[8];

    cudaFuncSetAttribute(cnf_kernel, cudaFuncAttributeMaxDynamicSharedMemorySize, SMEM_TOTAL);

    hyper_kernel<<<NSTAGE * 4, 256>>>(ts, w1, b1, w2, b2, w3, b3);
    cnf_kernel<<<NCTA, THREADS, SMEM_TOTAL>>>(ts, z0, lp0, (float*)d_out);
}

// round 9
// speedup vs baseline: 1.1702x; 1.0476x over previous
#include <cuda_runtime.h>
#include <cstdint>
#include <cstddef>

#define D        8
#define HIDDEN   64
#define WIDTH    128
#define NTOT     65536
#define TSTEPS   8
#define NSUB     4
#define NSEG     7
#define NSTAGE   84          // 7 segs * 4 substeps * 3 stage-times
#define ROWU2    9           // ulonglong2 (16B) per param row
#define NCTA     148
#define SPC      444         // samples per CTA (148*444 = 65712 >= 65536), multiple of 4
#define THREADS  256
#define HALFROWS 64
#define HALFOFS  (HALFROWS * ROWU2 + 1)   // skewed base of upper-half rows (+16B pad kills bank conflict)
#define BUFSZ    (WIDTH * ROWU2 + 1)

typedef unsigned long long u64;

// Per-stage parameter rows, duplicated for f32x2 consumption.
// Row k: [w0w0 ... w7w7 | u0u0 ... u7u7 | B B WU WU]   (U, WU pre-scaled by 1/WIDTH)
__device__ float4 gParams[NSTAGE * WIDTH * ROWU2];   // 1.548 MB static device scratch

// ---------------- f32x2 helpers ----------------
__device__ __forceinline__ u64 pack2(float x, float y) {
    u64 r; asm("mov.b64 %0, {%1, %2};" : "=l"(r) : "f"(x), "f"(y)); return r;
}
__device__ __forceinline__ void unpack2(u64 v, float& x, float& y) {
    asm("mov.b64 {%0, %1}, %2;" : "=f"(x), "=f"(y) : "l"(v));
}
__device__ __forceinline__ u64 fma2(u64 a, u64 b, u64 c) {
    u64 d; asm("fma.rn.f32x2 %0, %1, %2, %3;" : "=l"(d) : "l"(a), "l"(b), "l"(c)); return d;
}
__device__ __forceinline__ u64 add2(u64 a, u64 b) {
    u64 d; asm("add.rn.f32x2 %0, %1, %2;" : "=l"(d) : "l"(a), "l"(b)); return d;
}
__device__ __forceinline__ u64 mul2(u64 a, u64 b) {
    u64 d; asm("mul.rn.f32x2 %0, %1, %2;" : "=l"(d) : "l"(a), "l"(b)); return d;
}
__device__ __forceinline__ float tanh_fast(float x) {
    float y; asm("tanh.approx.f32 %0, %1;" : "=f"(y) : "f"(x)); return y;
}
__device__ __forceinline__ u64 tanh2(u64 v) {
    float x, y; unpack2(v, x, y);
    return pack2(tanh_fast(x), tanh_fast(y));
}
__device__ __forceinline__ u64 shx16(u64 v) {   // partner-combine across lane^16
    return (u64)__shfl_xor_sync(0xFFFFFFFFu, (unsigned long long)v, 16);
}

// ---------------- cp.async helpers ----------------
__device__ __forceinline__ void cp16(void* dst_smem, const void* src) {
    uint32_t d = (uint32_t)__cvta_generic_to_shared(dst_smem);
    asm volatile("cp.async.cg.shared.global [%0], [%1], 16;" :: "r"(d), "l"(src));
}
__device__ __forceinline__ void cp_commit() {
    asm volatile("cp.async.commit_group;");
}
__device__ __forceinline__ void cp_wait1() {
    asm volatile("cp.async.wait_group 1;");
}

// ---------------- Kernel A: hypernetwork, 4 blocks per stage, warp-per-row ----------------
__global__ void __launch_bounds__(256) hyper_kernel(
    const float* __restrict__ ts,
    const float* __restrict__ w1, const float* __restrict__ b1,
    const float* __restrict__ w2, const float* __restrict__ b2,
    const float* __restrict__ w3, const float* __restrict__ b3)
{
    const int s   = blockIdx.x >> 2;     // stage 0..83
    const int q   = blockIdx.x & 3;      // quarter 0..3
    const int seg = s / 12;
    const int sub = (s % 12) / 3;
    const int st  = s % 3;

    const float t0 = ts[seg];
    const float t1 = ts[seg + 1];
    const float dt = (t1 - t0) * (1.0f / NSUB);
    const float t  = t0 + sub * dt + (st == 0 ? 0.0f : (st == 1 ? 0.5f * dt : dt));

    __shared__ float h1s[HIDDEN];
    __shared__ float h2s[HIDDEN];
    __shared__ float ps[800];

    const int tid  = threadIdx.x;
    const int wrp  = tid >> 5;
    const int lane = tid & 31;

    if (tid < HIDDEN)
        h1s[tid] = tanhf(w1[tid] * t + b1[tid]);
    __syncthreads();

    if (tid < HIDDEN) {
        float acc = b2[tid];
        const float* wr = w2 + tid * HIDDEN;
        #pragma unroll 8
        for (int j = 0; j < HIDDEN; j++) acc += wr[j] * h1s[j];
        h2s[tid] = tanhf(acc);
    }
    __syncthreads();

    for (int i = wrp; i < 800; i += 8) {
        int r;
        if (i < 768) {
            const int chunk  = i >> 8;           // 0=W, 1=U, 2=G
            const int within = i & 255;
            r = chunk * (WIDTH * D) + q * 256 + within;
        } else {
            r = 3 * WIDTH * D + q * 32 + (i - 768);
        }
        const float* wr = w3 + (size_t)r * HIDDEN;
        float acc = wr[lane] * h2s[lane] + wr[lane + 32] * h2s[lane + 32];
        #pragma unroll
        for (int off = 16; off > 0; off >>= 1)
            acc += __shfl_xor_sync(0xFFFFFFFFu, acc, off);
        if (lane == 0) ps[i] = acc + b3[r];
    }
    __syncthreads();

    if (tid < 32) {
        const int kl = tid;
        const int k  = q * 32 + kl;
        float* out = (float*)gParams + ((size_t)s * WIDTH + k) * (ROWU2 * 4);
        const float B = ps[768 + kl];
        float wu = 0.0f;
        #pragma unroll
        for (int j = 0; j < D; j++) {
            const float W  = ps[kl * D + j];
            const float Ur = ps[256 + kl * D + j];
            const float G  = ps[512 + kl * D + j];
            const float U  = Ur * (1.0f / (1.0f + __expf(-G)));
            wu += W * U;
            const float Us = U * (1.0f / WIDTH);
            out[2 * j]          = W;  out[2 * j + 1]      = W;
            out[16 + 2 * j]     = Us; out[16 + 2 * j + 1] = Us;
        }
        const float wus = wu * (1.0f / WIDTH);
        out[32] = B;   out[33] = B;
        out[34] = wus; out[35] = wus;
    }
}

// ---------------- Kernel B: RK4, intra-warp pair per 4 samples, row-split ----------------

// Skewed fill: source index i, dest index i+1 for upper-half rows (bank-conflict pad).
__device__ __forceinline__ void prefetch_stage(ulonglong2* sp, const ulonglong2* __restrict__ src, int tid)
{
    #pragma unroll 1
    for (int i = tid; i < WIDTH * ROWU2; i += THREADS) {
        int d = i + (i >= HALFROWS * ROWU2 ? 1 : 0);
        cp16(sp + d, src + i);
    }
    cp_commit();
}

// Half-row RHS over 64 rows starting at rp0; partials combined via shfl.xor 16.
// zs/dz: 16 u64 = two groups of 2 packed samples; dl[2] trace accumulators.
__device__ __forceinline__ void rhs_half(const u64* __restrict__ zs, u64* __restrict__ dz,
                                         u64 dl[2], const ulonglong2* __restrict__ rp0)
{
    const u64 NEG1 = pack2(-1.0f, -1.0f);
    u64 tr0 = 0ULL, tr1 = 0ULL;
    #pragma unroll
    for (int j = 0; j < 16; j++) dz[j] = 0ULL;

    const ulonglong2* rp = rp0;
    #pragma unroll 2
    for (int k = 0; k < HALFROWS; k++, rp += ROWU2) {
        const ulonglong2 q0 = rp[0];
        const ulonglong2 q1 = rp[1];
        const ulonglong2 q2 = rp[2];
        const ulonglong2 q3 = rp[3];
        const ulonglong2 qb = rp[8];   // (B,B) , (WU',WU')

        u64 s0 = fma2(q0.x, zs[0], qb.x);
        u64 s1 = mul2(q0.y, zs[1]);
        s0 = fma2(q1.x, zs[2], s0);
        s1 = fma2(q1.y, zs[3], s1);
        s0 = fma2(q2.x, zs[4], s0);
        s1 = fma2(q2.y, zs[5], s1);
        s0 = fma2(q3.x, zs[6], s0);
        s1 = fma2(q3.y, zs[7], s1);

        u64 t0 = fma2(q0.x, zs[8],  qb.x);
        u64 t1 = mul2(q0.y, zs[9]);
        t0 = fma2(q1.x, zs[10], t0);
        t1 = fma2(q1.y, zs[11], t1);
        t0 = fma2(q2.x, zs[12], t0);
        t1 = fma2(q2.y, zs[13], t1);
        t0 = fma2(q3.x, zs[14], t0);
        t1 = fma2(q3.y, zs[15], t1);

        const u64 h0 = tanh2(add2(s0, s1));
        const u64 h1 = tanh2(add2(t0, t1));

        const ulonglong2 u0 = rp[4];
        const ulonglong2 u1 = rp[5];
        const ulonglong2 u2 = rp[6];
        const ulonglong2 u3 = rp[7];
        dz[0]  = fma2(h0, u0.x, dz[0]);
        dz[1]  = fma2(h0, u0.y, dz[1]);
        dz[2]  = fma2(h0, u1.x, dz[2]);
        dz[3]  = fma2(h0, u1.y, dz[3]);
        dz[4]  = fma2(h0, u2.x, dz[4]);
        dz[5]  = fma2(h0, u2.y, dz[5]);
        dz[6]  = fma2(h0, u3.x, dz[6]);
        dz[7]  = fma2(h0, u3.y, dz[7]);
        dz[8]  = fma2(h1, u0.x, dz[8]);
        dz[9]  = fma2(h1, u0.y, dz[9]);
        dz[10] = fma2(h1, u1.x, dz[10]);
        dz[11] = fma2(h1, u1.y, dz[11]);
        dz[12] = fma2(h1, u2.x, dz[12]);
        dz[13] = fma2(h1, u2.y, dz[13]);
        dz[14] = fma2(h1, u3.x, dz[14]);
        dz[15] = fma2(h1, u3.y, dz[15]);

        tr0 = fma2(fma2(h0, h0, NEG1), qb.y, tr0);
        tr1 = fma2(fma2(h1, h1, NEG1), qb.y, tr1);
    }

    // intra-warp partner combine (lane ^ 16): full-warp shuffles, no barriers
    #pragma unroll
    for (int j = 0; j < 16; j++) dz[j] = add2(dz[j], shx16(dz[j]));
    dl[0] = add2(tr0, shx16(tr0));
    dl[1] = add2(tr1, shx16(tr1));
}

__device__ __forceinline__ void store_group(float* __restrict__ out, int t, int n0,
                                            const u64* z, u64 lp)
{
    float a[D], b[D];
    #pragma unroll
    for (int j = 0; j < D; j++) unpack2(z[j], a[j], b[j]);
    float4* pz = (float4*)(out + (size_t)t * NTOT * D + (size_t)n0 * D);
    pz[0] = make_float4(a[0], a[1], a[2], a[3]);
    pz[1] = make_float4(a[4], a[5], a[6], a[7]);
    pz[2] = make_float4(b[0], b[1], b[2], b[3]);
    pz[3] = make_float4(b[4], b[5], b[6], b[7]);
    float la, lb; unpack2(lp, la, lb);
    float2* pl = (float2*)(out + (size_t)TSTEPS * NTOT * D + (size_t)t * NTOT + n0);
    *pl = make_float2(la, lb);
}

__global__ void __launch_bounds__(THREADS, 1) cnf_kernel(
    const float* __restrict__ ts,
    const float* __restrict__ z0,
    const float* __restrict__ lp0,
    float* __restrict__ out)
{
    __shared__ ulonglong2 spbuf[2][BUFSZ];    // 2 x 18448 B (with skew pad)

    const int tid   = threadIdx.x;
    const int lane  = tid & 31;
    const int half  = (lane >> 4) & 1;        // 0: rows 0-63, 1: rows 64-127
    const int slot  = (tid >> 5) * 16 + (lane & 15);   // quad id 0..127
    const int base  = blockIdx.x * SPC + slot * 4;
    const bool valid = (slot * 4 < SPC) && (base + 4 <= NTOT);
    const int hofs  = half ? HALFOFS : 0;

    const ulonglong2* gp = (const ulonglong2*)gParams;

    ulonglong2* bufA = spbuf[0];
    ulonglong2* bufB = spbuf[1];
    prefetch_stage(bufA, gp, tid);

    u64 z[16], lp[2];
    #pragma unroll
    for (int j = 0; j < 16; j++) z[j] = 0ULL;
    lp[0] = lp[1] = 0ULL;

    if (valid) {
        #pragma unroll
        for (int g = 0; g < 2; g++) {
            const int n0 = base + 2 * g;
            const float4* pa = (const float4*)(z0 + (size_t)n0 * D);
            const float4 a0 = pa[0], a1 = pa[1], b0 = pa[2], b1 = pa[3];
            z[8*g + 0] = pack2(a0.x, b0.x); z[8*g + 1] = pack2(a0.y, b0.y);
            z[8*g + 2] = pack2(a0.z, b0.z); z[8*g + 3] = pack2(a0.w, b0.w);
            z[8*g + 4] = pack2(a1.x, b1.x); z[8*g + 5] = pack2(a1.y, b1.y);
            z[8*g + 6] = pack2(a1.z, b1.z); z[8*g + 7] = pack2(a1.w, b1.w);
            const float2 l = *(const float2*)(lp0 + n0);
            lp[g] = pack2(l.x, l.y);
            if (half == 0) store_group(out, 0, n0, &z[8*g], lp[g]);
        }
    }

    for (int seg = 0; seg < NSEG; seg++) {
        const float dt  = (ts[seg + 1] - ts[seg]) * (1.0f / NSUB);
        const u64 dth = pack2(0.5f * dt, 0.5f * dt);
        const u64 dtf = pack2(dt, dt);
        const u64 dt6 = pack2(dt * (1.0f / 6.0f), dt * (1.0f / 6.0f));
        const u64 two = pack2(2.0f, 2.0f);

        for (int sub = 0; sub < NSUB; sub++) {
            const int sb = (seg * NSUB + sub) * 3;
            u64 acc[16], lacc[2], zs[16], dz[16], dl[2];

            // invariant: bufA has stage sb in flight (or landed)
            prefetch_stage(bufB, gp + (size_t)(sb + 1) * WIDTH * ROWU2, tid);
            cp_wait1();            // bufA landed
            __syncthreads();

            // k1 (bufA = sb) — all lanes compute (invalid lanes chew zeros)
            rhs_half(z, dz, dl, bufA + hofs);
            #pragma unroll
            for (int j = 0; j < 16; j++) { acc[j] = dz[j]; zs[j] = fma2(dth, dz[j], z[j]); }
            lacc[0] = dl[0]; lacc[1] = dl[1];

            __syncthreads();       // bufA reads done
            prefetch_stage(bufA, gp + (size_t)(sb + 2) * WIDTH * ROWU2, tid);
            cp_wait1();            // bufB landed
            __syncthreads();

            // k2 (bufB = sb+1)
            rhs_half(zs, dz, dl, bufB + hofs);
            #pragma unroll
            for (int j = 0; j < 16; j++) { acc[j] = fma2(two, dz[j], acc[j]); zs[j] = fma2(dth, dz[j], z[j]); }
            lacc[0] = fma2(two, dl[0], lacc[0]); lacc[1] = fma2(two, dl[1], lacc[1]);

            // k3 (bufB = sb+1, same params — no barrier needed)
            rhs_half(zs, dz, dl, bufB + hofs);
            #pragma unroll
            for (int j = 0; j < 16; j++) { acc[j] = fma2(two, dz[j], acc[j]); zs[j] = fma2(dtf, dz[j], z[j]); }
            lacc[0] = fma2(two, dl[0], lacc[0]); lacc[1] = fma2(two, dl[1], lacc[1]);

            __syncthreads();       // bufB reads done
            {
                int nxt = sb + 3; if (nxt >= NSTAGE) nxt = 0;
                prefetch_stage(bufB, gp + (size_t)nxt * WIDTH * ROWU2, tid);
            }
            cp_wait1();            // bufA (sb+2) landed
            __syncthreads();

            // k4 (bufA = sb+2)
            rhs_half(zs, dz, dl, bufA + hofs);
            #pragma unroll
            for (int j = 0; j < 16; j++) { acc[j] = add2(acc[j], dz[j]); z[j] = fma2(dt6, acc[j], z[j]); }
            lacc[0] = add2(lacc[0], dl[0]); lacc[1] = add2(lacc[1], dl[1]);
            lp[0] = fma2(dt6, lacc[0], lp[0]);
            lp[1] = fma2(dt6, lacc[1], lp[1]);

            __syncthreads();       // bufA reads done before next substep's prefetch overwrites

            ulonglong2* tmp = bufA; bufA = bufB; bufB = tmp;
        }
        if (valid && half == 0) {
            store_group(out, seg + 1, base,     &z[0], lp[0]);
            store_group(out, seg + 1, base + 2, &z[8], lp[1]);
        }
    }
}

// ---------------- launch ----------------
extern "C" void kernel_launch(void* const* d_in, const int* in_sizes, int n_in,
                              void* d_out, int out_size)
{
    const float* ts  = (const float*)d_in[0];
    const float* z0  = (const float*)d_in[1];
    const float* lp0 = (const float*)d_in[2];
    const float* w1  = (const float*)d_in[3];
    const float* b1  = (const float*)d_in[4];
    const float* w2  = (const float*)d_in[5];
    const float* b2  = (const float*)d_in[6];
    const float* w3  = (const float*)d_in[7];
    const float* b3  = (const float*)d_in[8];

    hyper_kernel<<<NSTAGE * 4, 256>>>(ts, w1, b1, w2, b2, w3, b3);
    cnf_kernel<<<NCTA, THREADS>>>(ts, z0, lp0, (float*)d_out);
}